// round 2
// baseline (speedup 1.0000x reference)
#include <cuda_runtime.h>
#include <cstdint>

#define THREADS 256

__global__ void __launch_bounds__(THREADS, 5) graphres_kernel(
    const float* __restrict__ x,
    const float* __restrict__ A_param,
    const float* __restrict__ W1,
    const float* __restrict__ b1,
    const float* __restrict__ W2,
    const float* __restrict__ b2,
    float* __restrict__ out,
    int nvec4)
{
    // Small working tables
    __shared__ float  sA8[6 * 8];      // softmax(A_param), rows padded to 8
    __shared__ float  st[36];          // sorted knots, padded with +INF (groups 0..8)
    __shared__ float2 sac[33];         // (slope, intercept) per segment
    __shared__ float  s_t[32], s_dA[32], s_dC[32];
    __shared__ float  so_dA[32], so_dC[32];
    // Lane-replicated tables, layout [slot][lane] -> conflict-free vector LDS
    __shared__ float4 rep4[9 * 32];    // knot groups of 4:  idx = (c>>2)*32 + lane
    __shared__ float2 repac[33 * 32];  // segment coeffs:    idx = c*32 + lane

    const int tid = threadIdx.x;
    const float INFF = __int_as_float(0x7f800000);

    // ---- preamble: softmax rows (threads 0..5) ----
    if (tid < 6) {
        float v[6];
        float mx = -3.4e38f;
        #pragma unroll
        for (int n = 0; n < 6; ++n) { v[n] = A_param[tid * 6 + n]; mx = fmaxf(mx, v[n]); }
        float s = 0.f;
        #pragma unroll
        for (int n = 0; n < 6; ++n) { v[n] = expf(v[n] - mx); s += v[n]; }
        float inv = 1.f / s;
        #pragma unroll
        for (int n = 0; n < 6; ++n) sA8[tid * 8 + n] = v[n] * inv;
        sA8[tid * 8 + 6] = 0.f;
        sA8[tid * 8 + 7] = 0.f;
    }
    // ---- knots + crossing deltas (threads 0..31) ----
    if (tid < 32) {
        float w1 = W1[tid], bb = b1[tid], w2 = W2[tid];
        float t, dA, dC;
        if (w1 > 0.f)      { t = -bb / w1; dA =  w1 * w2; dC =  bb * w2; }
        else if (w1 < 0.f) { t = -bb / w1; dA = -(w1 * w2); dC = -(bb * w2); }
        else               { t = INFF;     dA = 0.f;       dC = 0.f; }
        s_t[tid] = t; s_dA[tid] = dA; s_dC[tid] = dC;
    }
    if (tid >= 32 && tid < 36) st[tid] = INFF;   // pad group 8
    __syncthreads();

    // ---- rank-sort (stable) the 32 knots ----
    if (tid < 32) {
        float t = s_t[tid];
        int r = 0;
        #pragma unroll
        for (int j = 0; j < 32; ++j) {
            float tj = s_t[j];
            r += (tj < t || (tj == t && j < tid)) ? 1 : 0;
        }
        st[r] = t; so_dA[r] = s_dA[tid]; so_dC[r] = s_dC[tid];
    }
    __syncthreads();

    // ---- prefix: base segment (y -> -inf) then accumulate crossings ----
    if (tid == 0) {
        float a = 0.f, c = b2[0];
        for (int k = 0; k < 32; ++k) {
            float w1 = W1[k];
            if (w1 < 0.f)       { a += w1 * W2[k]; c += b1[k] * W2[k]; }
            else if (w1 == 0.f) { c += fmaxf(b1[k], 0.f) * W2[k]; }
        }
        sac[0] = make_float2(a, c);
        for (int j = 0; j < 32; ++j) {
            a += so_dA[j]; c += so_dC[j];
            sac[j + 1] = make_float2(a, c);
        }
    }
    __syncthreads();

    // ---- replicate tables per lane ----
    for (int i = tid; i < 9 * 32; i += THREADS) {
        int g = i >> 5;
        rep4[i] = make_float4(st[g * 4 + 0], st[g * 4 + 1], st[g * 4 + 2], st[g * 4 + 3]);
    }
    for (int i = tid; i < 33 * 32; i += THREADS) repac[i] = sac[i >> 5];

    // register-resident top-of-ladder knots
    const float k31 = st[31];
    const float k15 = st[15];
    const float k7  = st[7],  k23 = st[23];
    const float k3  = st[3],  k11 = st[11], k19 = st[19], k27 = st[27];
    __syncthreads();

    const int lane = tid & 31;
    const float4* kp4 = rep4  + lane;
    const float2* acp = repac + lane;
    const uint32_t aBase = (uint32_t)__cvta_generic_to_shared(sA8);

    const float4* xin  = (const float4*)x;
    float4*       xout = (float4*)out;
    const int gt   = blockIdx.x * THREADS + tid;
    const int base = gt * 12;   // 12 float4 = 8 rows per thread

    #pragma unroll 1
    for (int it = 0; it < 4; ++it) {
        const int b0 = base + it * 3;           // 3 float4 = 2 rows
        if (b0 + 3 > nvec4) break;
        float4 v0 = xin[b0 + 0];
        float4 v1 = xin[b0 + 1];
        float4 v2 = xin[b0 + 2];
        float xr[12] = { v0.x, v0.y, v0.z, v0.w,
                         v1.x, v1.y, v1.z, v1.w,
                         v2.x, v2.y, v2.z, v2.w };
        float yv[12];

        // matvec: y = A @ x for both rows; A rows streamed from smem
        // (volatile loads so they are NOT hoisted into persistent registers)
        #pragma unroll
        for (int m = 0; m < 6; ++m) {
            float a0, a1, a2, a3, a4, a5;
            uint32_t aaddr = aBase + (uint32_t)(m * 32);
            asm volatile("ld.shared.v4.f32 {%0,%1,%2,%3},[%4];"
                         : "=f"(a0), "=f"(a1), "=f"(a2), "=f"(a3) : "r"(aaddr));
            asm volatile("ld.shared.v2.f32 {%0,%1},[%2];"
                         : "=f"(a4), "=f"(a5) : "r"(aaddr + 16u));
            {
                float pa = a0 * xr[0];
                float pb = a1 * xr[1];
                pa = fmaf(a2, xr[2], pa);
                pb = fmaf(a3, xr[3], pb);
                pa = fmaf(a4, xr[4], pa);
                pb = fmaf(a5, xr[5], pb);
                yv[m] = pa + pb;
            }
            {
                float pa = a0 * xr[6];
                float pb = a1 * xr[7];
                pa = fmaf(a2, xr[8],  pa);
                pb = fmaf(a3, xr[9],  pb);
                pa = fmaf(a4, xr[10], pa);
                pb = fmaf(a5, xr[11], pb);
                yv[6 + m] = pa + pb;
            }
        }

        // piecewise-linear eval: 4 register levels + 1 LDS.128 + 2 register
        // levels + 1 LDS.64
        float ov[12];
        #pragma unroll
        for (int e = 0; e < 12; ++e) {
            float y = yv[e];
            bool top = (y > k31);
            int c = top ? 32 : 0;
            float t2 = top ? INFF : k15;
            if (y > t2) c += 16;
            float t3 = (c & 16) ? k23 : k7;
            t3 = top ? INFF : t3;
            if (y > t3) c += 8;
            float ta = (c & 8) ? k11 : k3;
            float tb = (c & 8) ? k27 : k19;
            float t4 = (c & 16) ? tb : ta;
            t4 = top ? INFF : t4;
            if (y > t4) c += 4;
            // c is now a multiple of 4 in [0,32]
            float4 kt = kp4[c << 3];          // rep4[(c>>2)*32 + lane]
            int add2 = (y > kt.y) ? 2 : 0;
            float t6 = add2 ? kt.z : kt.x;
            c += add2 + ((y > t6) ? 1 : 0);
            float2 ac = acp[c << 5];          // repac[c*32 + lane]
            ov[e] = fmaf(ac.x, y, ac.y) + xr[e];
        }

        xout[b0 + 0] = make_float4(ov[0], ov[1], ov[2],  ov[3]);
        xout[b0 + 1] = make_float4(ov[4], ov[5], ov[6],  ov[7]);
        xout[b0 + 2] = make_float4(ov[8], ov[9], ov[10], ov[11]);
    }
}

extern "C" void kernel_launch(void* const* d_in, const int* in_sizes, int n_in,
                              void* d_out, int out_size)
{
    const float* x  = (const float*)d_in[0];
    const float* Ap = (const float*)d_in[1];
    const float* W1 = (const float*)d_in[2];
    const float* b1 = (const float*)d_in[3];
    const float* W2 = (const float*)d_in[4];
    const float* b2 = (const float*)d_in[5];
    float* out = (float*)d_out;

    int nvec4 = out_size / 4;                       // total float4s (B*N/4)
    int threads_total = (nvec4 + 11) / 12;          // 12 float4 per thread
    int grid = (threads_total + THREADS - 1) / THREADS;
    graphres_kernel<<<grid, THREADS>>>(x, Ap, W1, b1, W2, b2, out, nvec4);
}

// round 5
// speedup vs baseline: 1.2301x; 1.2301x over previous
#include <cuda_runtime.h>
#include <cstdint>

#define THREADS 256

// Tables computed once per replay by the setup kernel
__device__ float  g_A[48];     // softmax(A_param), 6 rows padded to 8
__device__ float  g_k8[8];     // ladder levels 1-4: t31,t15,t7,t23,t3,t11,t19,t27
__device__ float  g_t5[9];     // level 5 knots t1,t5,...,t29, +INF pad
__device__ float4 g_pl[17];    // per segment-pair (a, b, dA, t)

__global__ void setup_kernel(const float* __restrict__ A_param,
                             const float* __restrict__ W1,
                             const float* __restrict__ b1,
                             const float* __restrict__ W2,
                             const float* __restrict__ b2)
{
    __shared__ float s_t[32], s_dA[32], s_dC[32];
    __shared__ float st[32],  sdA[32],  sdC[32];
    const int tid = threadIdx.x;  // 32 threads
    const float INFF = __int_as_float(0x7f800000);

    // softmax rows of A_param
    if (tid < 6) {
        float v[6];
        float mx = -3.4e38f;
        #pragma unroll
        for (int n = 0; n < 6; ++n) { v[n] = A_param[tid * 6 + n]; mx = fmaxf(mx, v[n]); }
        float s = 0.f;
        #pragma unroll
        for (int n = 0; n < 6; ++n) { v[n] = expf(v[n] - mx); s += v[n]; }
        float inv = 1.f / s;
        #pragma unroll
        for (int n = 0; n < 6; ++n) g_A[tid * 8 + n] = v[n] * inv;
        g_A[tid * 8 + 6] = 0.f;
        g_A[tid * 8 + 7] = 0.f;
    }

    // knots + crossing deltas
    {
        float w1 = W1[tid], bb = b1[tid], w2 = W2[tid];
        float t, dA, dC;
        if (w1 > 0.f)      { t = -bb / w1; dA =  w1 * w2;  dC =  bb * w2; }
        else if (w1 < 0.f) { t = -bb / w1; dA = -(w1 * w2); dC = -(bb * w2); }
        else               { t = INFF;     dA = 0.f;        dC = 0.f; }
        s_t[tid] = t; s_dA[tid] = dA; s_dC[tid] = dC;
    }
    __syncthreads();

    // stable rank-sort of the 32 knots
    {
        float t = s_t[tid];
        int r = 0;
        #pragma unroll
        for (int j = 0; j < 32; ++j) {
            float tj = s_t[j];
            r += (tj < t || (tj == t && j < tid)) ? 1 : 0;
        }
        st[r] = t; sdA[r] = s_dA[tid]; sdC[r] = s_dC[tid];
    }
    __syncthreads();

    if (tid == 0) {
        // base segment (y -> -inf), then prefix over crossings
        float a = 0.f, c = b2[0];
        for (int k = 0; k < 32; ++k) {
            float w1 = W1[k];
            if (w1 < 0.f)       { a += w1 * W2[k]; c += b1[k] * W2[k]; }
            else if (w1 == 0.f) { c += fmaxf(b1[k], 0.f) * W2[k]; }
        }
        float aa[33], cc[33];
        aa[0] = a; cc[0] = c;
        for (int j = 0; j < 32; ++j) {
            a += sdA[j]; c += sdC[j];
            aa[j + 1] = a; cc[j + 1] = c;
        }
        // pair entries: segments (2g, 2g+1) meet at knot st[2g]
        for (int g = 0; g < 16; ++g)
            g_pl[g] = make_float4(aa[2 * g], cc[2 * g], sdA[2 * g], st[2 * g]);
        g_pl[16] = make_float4(aa[32], cc[32], 0.f, INFF);
        // level-5 knots (t[c+1] for c = 0,4,...,28), pad for c=32
        for (int i = 0; i < 8; ++i) g_t5[i] = st[4 * i + 1];
        g_t5[8] = INFF;
        // levels 1-4 knots
        g_k8[0] = st[31]; g_k8[1] = st[15];
        g_k8[2] = st[7];  g_k8[3] = st[23];
        g_k8[4] = st[3];  g_k8[5] = st[11];
        g_k8[6] = st[19]; g_k8[7] = st[27];
    }
}

__global__ void __launch_bounds__(THREADS, 5) graphres_main(
    const float4* __restrict__ x,
    float4* __restrict__ out,
    int nvec4)
{
    // Lane-replicated tables, layout [slot][lane] -> conflict-free divergent LDS
    __shared__ float4 repPL[17 * 32];
    __shared__ float  repT5[9 * 32];
    __shared__ float  sA[48];

    const int tid = threadIdx.x;
    const float INFF = __int_as_float(0x7f800000);

    if (tid < 48) sA[tid] = g_A[tid];
    for (int i = tid; i < 17 * 32; i += THREADS) repPL[i] = g_pl[i >> 5];
    for (int i = tid; i < 9 * 32;  i += THREADS) repT5[i] = g_t5[i >> 5];

    const float k31 = g_k8[0], k15 = g_k8[1];
    const float k7  = g_k8[2], k23 = g_k8[3];
    const float k3  = g_k8[4], k11 = g_k8[5], k19 = g_k8[6], k27 = g_k8[7];
    __syncthreads();

    const int lane = tid & 31;
    const float4* plp = repPL + lane;
    const float*  t5p = repT5 + lane;
    const uint32_t aBase = (uint32_t)__cvta_generic_to_shared(sA);

    const int gt = blockIdx.x * THREADS + tid;
    const int b0 = gt * 3;                 // 3 float4 = 2 rows of 6
    if (b0 + 3 > nvec4) return;

    float4 v0 = x[b0 + 0];
    float4 v1 = x[b0 + 1];
    float4 v2 = x[b0 + 2];
    float xr[12] = { v0.x, v0.y, v0.z, v0.w,
                     v1.x, v1.y, v1.z, v1.w,
                     v2.x, v2.y, v2.z, v2.w };
    float yv[12];

    // matvec y = A @ x for both rows (A rows broadcast from smem)
    #pragma unroll
    for (int m = 0; m < 6; ++m) {
        float a0, a1, a2, a3, a4, a5;
        uint32_t aaddr = aBase + (uint32_t)(m * 32);
        asm volatile("ld.shared.v4.f32 {%0,%1,%2,%3},[%4];"
                     : "=f"(a0), "=f"(a1), "=f"(a2), "=f"(a3) : "r"(aaddr));
        asm volatile("ld.shared.v2.f32 {%0,%1},[%2];"
                     : "=f"(a4), "=f"(a5) : "r"(aaddr + 16u));
        {
            float pa = a0 * xr[0];
            float pb = a1 * xr[1];
            pa = fmaf(a2, xr[2], pa);
            pb = fmaf(a3, xr[3], pb);
            pa = fmaf(a4, xr[4], pa);
            pb = fmaf(a5, xr[5], pb);
            yv[m] = pa + pb;
        }
        {
            float pa = a0 * xr[6];
            float pb = a1 * xr[7];
            pa = fmaf(a2, xr[8],  pa);
            pb = fmaf(a3, xr[9],  pb);
            pa = fmaf(a4, xr[10], pa);
            pb = fmaf(a5, xr[11], pb);
            yv[6 + m] = pa + pb;
        }
    }

    // piecewise-linear eval: 4 register levels + LDS.32 (level 5)
    // + LDS.128 pair fetch; last level folded into relu
    float ov[12];
    #pragma unroll
    for (int e = 0; e < 12; ++e) {
        float y = yv[e];
        bool top = (y > k31);
        int c = top ? 32 : 0;
        float t2 = top ? INFF : k15;
        bool b16 = (y > t2);
        if (b16) c += 16;
        float t3 = b16 ? k23 : k7;
        t3 = top ? INFF : t3;
        bool b8 = (y > t3);
        if (b8) c += 8;
        float ta = b8 ? k11 : k3;
        float tb = b8 ? k27 : k19;
        float t4 = b16 ? tb : ta;
        t4 = top ? INFF : t4;
        if (y > t4) c += 4;
        float t5 = t5p[(c >> 2) << 5];         // repT5[(c>>2)*32 + lane]
        if (y > t5) c += 2;
        float4 pe = plp[(c >> 1) << 5];        // repPL[(c>>1)*32 + lane]
        float r = fmaf(pe.z, fmaxf(y - pe.w, 0.f), fmaf(pe.x, y, pe.y));
        ov[e] = r + xr[e];
    }

    out[b0 + 0] = make_float4(ov[0], ov[1], ov[2],  ov[3]);
    out[b0 + 1] = make_float4(ov[4], ov[5], ov[6],  ov[7]);
    out[b0 + 2] = make_float4(ov[8], ov[9], ov[10], ov[11]);
}

extern "C" void kernel_launch(void* const* d_in, const int* in_sizes, int n_in,
                              void* d_out, int out_size)
{
    const float* x  = (const float*)d_in[0];
    const float* Ap = (const float*)d_in[1];
    const float* W1 = (const float*)d_in[2];
    const float* b1 = (const float*)d_in[3];
    const float* W2 = (const float*)d_in[4];
    const float* b2 = (const float*)d_in[5];
    float* out = (float*)d_out;

    int nvec4 = out_size / 4;                       // total float4s (B*N/4)
    int threads_total = (nvec4 + 2) / 3;            // 3 float4 per thread
    int grid = (threads_total + THREADS - 1) / THREADS;

    setup_kernel<<<1, 32>>>(Ap, W1, b1, W2, b2);
    graphres_main<<<grid, THREADS>>>((const float4*)x, (float4*)out, nvec4);
}